// round 16
// baseline (speedup 1.0000x reference)
#include <cuda_runtime.h>

// Integer-exact fused QAT conv stack (bit-exact vs fp32 reference).
// Final: R9 3-stage smem design (best measured) + evict-first output stores.
// TL=2048, NT=256, 6 blocks/SM, 40 regs, 24.6KB smem.

#define TL 2048      // tile positions per block
#define NT 256       // threads per block

__device__ __forceinline__ int cvtrd(float v) {
    return __float2int_rd(fmaf(v, 128.0f, 0.5f));   // floor(v*128 + 0.5)
}
__device__ __forceinline__ int packsat2(int a, int b, int c) {
    int d;
    asm("cvt.pack.sat.s8.s32.b32 %0, %1, %2, %3;"
        : "=r"(d) : "r"(a), "r"(b), "r"(c));
    return d;
}
// bytes perm of [v0..v3]; same helper for weights and data -> dp4a invariant
__device__ __forceinline__ int pack4sat(int v0, int v1, int v2, int v3) {
    return packsat2(v1, v0, packsat2(v3, v2, 0));
}
__device__ __forceinline__ int qpack(float a, float b, float c, float d) {
    return pack4sat(cvtrd(a), cvtrd(b), cvtrd(c), cvtrd(d));
}

// Stages 2+3, templated on EDGE so interior blocks get a branch-free body.
// wsh: [0..23] w1p (oc*3+k), [24..31] bo1, [32..43] w2p, [44..45] bo2
template <bool EDGE>
__device__ __forceinline__ void stages23(
    const int* __restrict__ xs, int* __restrict__ ysL, int* __restrict__ ysH,
    const int* __restrict__ wsh, int tid, int ts, int L, float* __restrict__ ob)
{
    // ---- stage 2: y = satpack((conv1 + 128*b + 64) >> 7), 4 pos/thread ----
    for (int g = tid; g < (TL + 4) / 4; g += NT) {
        int m = 4 * g;
        int4 va = *(const int4*)(xs + m);
        int4 vb = *(const int4*)(xs + m + 4);
        int xv[8] = {va.x, va.y, va.z, va.w, vb.x, vb.y, vb.z, vb.w};
        int lo[4], hi[4];
#pragma unroll
        for (int p = 0; p < 4; p++) {
            int x0 = xv[p + 1], x1 = xv[p + 2], x2 = xv[p + 3];
            int yv[8];
#pragma unroll
            for (int oc = 0; oc < 8; oc++) {
                int acc = __dp4a(x0, wsh[oc * 3 + 0], wsh[24 + oc]);
                acc     = __dp4a(x1, wsh[oc * 3 + 1], acc);
                acc     = __dp4a(x2, wsh[oc * 3 + 2], acc);
                yv[oc]  = acc >> 7;
            }
            lo[p] = pack4sat(yv[0], yv[1], yv[2], yv[3]);
            hi[p] = pack4sat(yv[4], yv[5], yv[6], yv[7]);
            if (EDGE) {
                int q = ts - 2 + m + p;
                bool valid = (q >= 0) && (q < L);
                lo[p] = valid ? lo[p] : 0;
                hi[p] = valid ? hi[p] : 0;
            }
        }
        *(int4*)(ysL + m) = make_int4(lo[0], lo[1], lo[2], lo[3]);
        *(int4*)(ysH + m) = make_int4(hi[0], hi[1], hi[2], hi[3]);
    }
    __syncthreads();

    // ---- stage 3: z = dequant(clamp((conv2 + 128*b + 64) >> 7)), 4 pos ----
    for (int g = tid; g < TL / 4; g += NT) {
        int j = 4 * g;
        int4 la = *(const int4*)(ysL + j);
        int4 lb = *(const int4*)(ysL + j + 4);
        int4 ha = *(const int4*)(ysH + j);
        int4 hb = *(const int4*)(ysH + j + 4);
        int YL[8] = {la.x, la.y, la.z, la.w, lb.x, lb.y, lb.z, lb.w};
        int YH[8] = {ha.x, ha.y, ha.z, ha.w, hb.x, hb.y, hb.z, hb.w};
        float f0[4], f1[4];
#pragma unroll
        for (int p = 0; p < 4; p++) {
            int a0 = __dp4a(YL[p + 1], wsh[32], wsh[44]);
            a0     = __dp4a(YH[p + 1], wsh[33], a0);
            a0     = __dp4a(YL[p + 2], wsh[34], a0);
            a0     = __dp4a(YH[p + 2], wsh[35], a0);
            a0     = __dp4a(YL[p + 3], wsh[36], a0);
            a0     = __dp4a(YH[p + 3], wsh[37], a0);
            int a1 = __dp4a(YL[p + 1], wsh[38], wsh[45]);
            a1     = __dp4a(YH[p + 1], wsh[39], a1);
            a1     = __dp4a(YL[p + 2], wsh[40], a1);
            a1     = __dp4a(YH[p + 2], wsh[41], a1);
            a1     = __dp4a(YL[p + 3], wsh[42], a1);
            a1     = __dp4a(YH[p + 3], wsh[43], a1);
            f0[p] = (float)min(max(a0 >> 7, -128), 127) * 0.0078125f;
            f1[p] = (float)min(max(a1 >> 7, -128), 127) * 0.0078125f;
        }
        __stcs((float4*)(ob + ts + j),
               make_float4(f0[0], f0[1], f0[2], f0[3]));
        __stcs((float4*)(ob + (size_t)L + ts + j),
               make_float4(f1[0], f1[1], f1[2], f1[3]));
    }
}

__global__ __launch_bounds__(NT, 6) void fused_qconv_v16(
    const float* __restrict__ x,
    const float* __restrict__ w1, const float* __restrict__ b1,
    const float* __restrict__ gamma, const float* __restrict__ beta,
    const float* __restrict__ bn_mean, const float* __restrict__ bn_var,
    const float* __restrict__ w2, const float* __restrict__ b2,
    float* __restrict__ out, int L)
{
    __shared__ int wsh[48];
    extern __shared__ int smem[];
    int* xs  = smem;                 // [TL+8]  packed x, xs[i] = pos ts-4+i
    int* ysL = smem + (TL + 8);      // [TL+4]  y ch0..3, ysL[i] = pos ts-2+i
    int* ysH = ysL + (TL + 4);       // [TL+4]  y ch4..7

    const int tid = threadIdx.x;
    const int bb  = blockIdx.y;
    const int ts  = blockIdx.x * TL;
    const float* xb = x + (size_t)bb * 4 * L;
    const bool edge = (blockIdx.x == 0) | (blockIdx.x == gridDim.x - 1);

    // ---- halos + tiny weight set (disjoint tid ranges) ----
    if (tid < 4) {                                // left halo: pos ts-4+tid
        int p = ts - 4 + tid, w = 0;
        if (p >= 0)
            w = qpack(xb[p], xb[(size_t)L + p],
                      xb[(size_t)2*L + p], xb[(size_t)3*L + p]);
        xs[tid] = w;
    } else if (tid < 8) {                         // right halo
        int p = ts + TL + (tid - 4), w = 0;
        if (p < L)
            w = qpack(xb[p], xb[(size_t)L + p],
                      xb[(size_t)2*L + p], xb[(size_t)3*L + p]);
        xs[TL + 4 + (tid - 4)] = w;
    } else if (tid >= 32 && tid < 56) {           // w1 packed
        int t = tid - 32, oc = t / 3, k = t % 3;
        float sf = (float)((double)gamma[oc] / sqrt((double)bn_var[oc] + 1e-5));
        const float* wb = w1 + oc * 12 + k;
        wsh[t] = qpack(wb[0] * sf, wb[3] * sf, wb[6] * sf, wb[9] * sf);
    } else if (tid >= 56 && tid < 64) {           // folded bias 1
        int oc = tid - 56;
        float sf = (float)((double)gamma[oc] / sqrt((double)bn_var[oc] + 1e-5));
        int bi = min(max(cvtrd((b1[oc] - bn_mean[oc]) * sf + beta[oc]), -128), 127);
        wsh[24 + oc] = bi * 128 + 64;
    } else if (tid >= 64 && tid < 76) {           // w2 packed
        int t = tid - 64, oc = t / 6, r = t % 6, k = r >> 1, h = r & 1;
        const float* wb = w2 + oc * 24 + h * 12 + k;
        wsh[32 + t] = qpack(wb[0], wb[3], wb[6], wb[9]);
    } else if (tid >= 76 && tid < 78) {           // bias 2
        int oc = tid - 76;
        wsh[44 + oc] = min(max(cvtrd(b2[oc]), -128), 127) * 128 + 64;
    }

    // ---- stage 1: float4 load + quantize + pack 4 ch/word ----
    for (int g = tid; g < TL / 4; g += NT) {
        int p = ts + 4 * g;
        float4 a = *(const float4*)(xb + p);
        float4 b = *(const float4*)(xb + (size_t)L + p);
        float4 c = *(const float4*)(xb + (size_t)2 * L + p);
        float4 d = *(const float4*)(xb + (size_t)3 * L + p);
        int4 w;
        w.x = qpack(a.x, b.x, c.x, d.x);
        w.y = qpack(a.y, b.y, c.y, d.y);
        w.z = qpack(a.z, b.z, c.z, d.z);
        w.w = qpack(a.w, b.w, c.w, d.w);
        *(int4*)(xs + 4 + 4 * g) = w;
    }
    __syncthreads();

    float* ob = out + (size_t)bb * 2 * L;
    if (edge) stages23<true >(xs, ysL, ysH, wsh, tid, ts, L, ob);
    else      stages23<false>(xs, ysL, ysH, wsh, tid, ts, L, ob);
}

extern "C" void kernel_launch(void* const* d_in, const int* in_sizes, int n_in,
                              void* d_out, int out_size)
{
    const float* x       = (const float*)d_in[0];
    const float* w1      = (const float*)d_in[1];
    const float* b1      = (const float*)d_in[2];
    const float* gamma   = (const float*)d_in[3];
    const float* beta    = (const float*)d_in[4];
    const float* bn_mean = (const float*)d_in[5];
    const float* bn_var  = (const float*)d_in[6];
    const float* w2      = (const float*)d_in[7];
    const float* b2      = (const float*)d_in[8];
    float* out = (float*)d_out;

    const int B = 16;
    const int L = in_sizes[0] / (B * 4);

    const int smem_bytes = ((TL + 8) + 2 * (TL + 4)) * (int)sizeof(int); // 24.6KB

    dim3 grid((L + TL - 1) / TL, B);
    fused_qconv_v16<<<grid, NT, smem_bytes>>>(
        x, w1, b1, gamma, beta, bn_mean, bn_var, w2, b2, out, L);
}

// round 17
// speedup vs baseline: 1.0789x; 1.0789x over previous
#include <cuda_runtime.h>

// Integer-exact fused QAT conv stack (bit-exact vs fp32 reference).
// FINAL (session best, R9): 3-stage smem design.
//   stage 1: float4 load x, fake-quant to int8, pack 4 channels/word
//   stage 2: conv1 via DP4A, requant (+64)>>7 with cvt.pack.sat.s8
//   stage 3: conv2 via DP4A, requant, dequant to fp32, float4 store
// TL=2048, NT=256, __launch_bounds__(256,6): 40 regs, 24.6KB smem,
// 6 blocks/SM. Measured: 51.9us wall / 48.4us ncu, rel_err = 0.

#define TL 2048      // tile positions per block
#define NT 256       // threads per block

__device__ __forceinline__ int cvtrd(float v) {
    return __float2int_rd(fmaf(v, 128.0f, 0.5f));   // floor(v*128 + 0.5)
}
__device__ __forceinline__ int packsat2(int a, int b, int c) {
    int d;
    asm("cvt.pack.sat.s8.s32.b32 %0, %1, %2, %3;"
        : "=r"(d) : "r"(a), "r"(b), "r"(c));
    return d;
}
// bytes perm of [v0..v3]; same helper for weights and data -> dp4a invariant
__device__ __forceinline__ int pack4sat(int v0, int v1, int v2, int v3) {
    return packsat2(v1, v0, packsat2(v3, v2, 0));
}
__device__ __forceinline__ int qpack(float a, float b, float c, float d) {
    return pack4sat(cvtrd(a), cvtrd(b), cvtrd(c), cvtrd(d));
}

__global__ __launch_bounds__(NT, 6) void fused_qconv_i8o(
    const float* __restrict__ x,
    const float* __restrict__ w1, const float* __restrict__ b1,
    const float* __restrict__ gamma, const float* __restrict__ beta,
    const float* __restrict__ bn_mean, const float* __restrict__ bn_var,
    const float* __restrict__ w2, const float* __restrict__ b2,
    float* __restrict__ out, int L)
{
    __shared__ int w1p[8][3];        // conv1 w: 4 in-ch packed per (oc,k)
    __shared__ int bo1[8];           // 128*b1_int + 64
    __shared__ int w2p[2][3][2];     // conv2 w: [oc][k][half]
    __shared__ int bo2[2];           // 128*b2_int + 64
    extern __shared__ int smem[];
    int* xs  = smem;                 // [TL+8]  packed x, xs[i] = pos ts-4+i
    int* ysL = smem + (TL + 8);      // [TL+4]  y ch0..3, ysL[i] = pos ts-2+i
    int* ysH = ysL + (TL + 4);       // [TL+4]  y ch4..7

    const int tid = threadIdx.x;
    const int bb  = blockIdx.y;
    const int ts  = blockIdx.x * TL;
    const float* xb = x + (size_t)bb * 4 * L;
    const bool edge = (blockIdx.x == 0) | (blockIdx.x == gridDim.x - 1);

    // ---- halos + tiny weight set (disjoint tid ranges) ----
    if (tid < 4) {                                // left halo: pos ts-4+tid
        int p = ts - 4 + tid, w = 0;
        if (p >= 0)
            w = qpack(xb[p], xb[(size_t)L + p],
                      xb[(size_t)2*L + p], xb[(size_t)3*L + p]);
        xs[tid] = w;
    } else if (tid < 8) {                         // right halo
        int p = ts + TL + (tid - 4), w = 0;
        if (p < L)
            w = qpack(xb[p], xb[(size_t)L + p],
                      xb[(size_t)2*L + p], xb[(size_t)3*L + p]);
        xs[TL + 4 + (tid - 4)] = w;
    } else if (tid >= 32 && tid < 56) {           // w1 packed
        int t = tid - 32, oc = t / 3, k = t % 3;
        float sf = (float)((double)gamma[oc] / sqrt((double)bn_var[oc] + 1e-5));
        const float* wb = w1 + oc * 12 + k;
        w1p[oc][k] = qpack(wb[0] * sf, wb[3] * sf, wb[6] * sf, wb[9] * sf);
    } else if (tid >= 56 && tid < 64) {           // folded bias 1
        int oc = tid - 56;
        float sf = (float)((double)gamma[oc] / sqrt((double)bn_var[oc] + 1e-5));
        int bi = min(max(cvtrd((b1[oc] - bn_mean[oc]) * sf + beta[oc]), -128), 127);
        bo1[oc] = bi * 128 + 64;
    } else if (tid >= 64 && tid < 76) {           // w2 packed
        int t = tid - 64, oc = t / 6, r = t % 6, k = r >> 1, h = r & 1;
        const float* wb = w2 + oc * 24 + h * 12 + k;
        w2p[oc][k][h] = qpack(wb[0], wb[3], wb[6], wb[9]);
    } else if (tid >= 76 && tid < 78) {           // bias 2
        int oc = tid - 76;
        bo2[oc] = min(max(cvtrd(b2[oc]), -128), 127) * 128 + 64;
    }

    // ---- stage 1: float4 load + quantize + pack 4 ch/word ----
    for (int g = tid; g < TL / 4; g += NT) {
        int p = ts + 4 * g;
        float4 a = *(const float4*)(xb + p);
        float4 b = *(const float4*)(xb + (size_t)L + p);
        float4 c = *(const float4*)(xb + (size_t)2 * L + p);
        float4 d = *(const float4*)(xb + (size_t)3 * L + p);
        int4 w;
        w.x = qpack(a.x, b.x, c.x, d.x);
        w.y = qpack(a.y, b.y, c.y, d.y);
        w.z = qpack(a.z, b.z, c.z, d.z);
        w.w = qpack(a.w, b.w, c.w, d.w);
        *(int4*)(xs + 4 + 4 * g) = w;
    }
    __syncthreads();

    // ---- stage 2: y = satpack((conv1 + 128*b + 64) >> 7), 4 pos/thread ----
    for (int g = tid; g < (TL + 4) / 4; g += NT) {
        int m = 4 * g;
        int4 va = *(const int4*)(xs + m);
        int4 vb = *(const int4*)(xs + m + 4);
        int xv[8] = {va.x, va.y, va.z, va.w, vb.x, vb.y, vb.z, vb.w};
        int lo[4], hi[4];
#pragma unroll
        for (int p = 0; p < 4; p++) {
            int x0 = xv[p + 1], x1 = xv[p + 2], x2 = xv[p + 3];
            int yv[8];
#pragma unroll
            for (int oc = 0; oc < 8; oc++) {
                int acc = __dp4a(x0, w1p[oc][0], bo1[oc]);
                acc     = __dp4a(x1, w1p[oc][1], acc);
                acc     = __dp4a(x2, w1p[oc][2], acc);
                yv[oc]  = acc >> 7;
            }
            lo[p] = pack4sat(yv[0], yv[1], yv[2], yv[3]);
            hi[p] = pack4sat(yv[4], yv[5], yv[6], yv[7]);
            if (edge) {
                int q = ts - 2 + m + p;
                bool valid = (q >= 0) && (q < L);
                lo[p] = valid ? lo[p] : 0;
                hi[p] = valid ? hi[p] : 0;
            }
        }
        *(int4*)(ysL + m) = make_int4(lo[0], lo[1], lo[2], lo[3]);
        *(int4*)(ysH + m) = make_int4(hi[0], hi[1], hi[2], hi[3]);
    }
    __syncthreads();

    // ---- stage 3: z = dequant(clamp((conv2 + 128*b + 64) >> 7)), 4 pos ----
    float* ob = out + (size_t)bb * 2 * L;
    for (int g = tid; g < TL / 4; g += NT) {
        int j = 4 * g;
        int4 la = *(const int4*)(ysL + j);
        int4 lb = *(const int4*)(ysL + j + 4);
        int4 ha = *(const int4*)(ysH + j);
        int4 hb = *(const int4*)(ysH + j + 4);
        int YL[8] = {la.x, la.y, la.z, la.w, lb.x, lb.y, lb.z, lb.w};
        int YH[8] = {ha.x, ha.y, ha.z, ha.w, hb.x, hb.y, hb.z, hb.w};
        float f0[4], f1[4];
#pragma unroll
        for (int p = 0; p < 4; p++) {
            int a0 = __dp4a(YL[p + 1], w2p[0][0][0], bo2[0]);
            a0     = __dp4a(YH[p + 1], w2p[0][0][1], a0);
            a0     = __dp4a(YL[p + 2], w2p[0][1][0], a0);
            a0     = __dp4a(YH[p + 2], w2p[0][1][1], a0);
            a0     = __dp4a(YL[p + 3], w2p[0][2][0], a0);
            a0     = __dp4a(YH[p + 3], w2p[0][2][1], a0);
            int a1 = __dp4a(YL[p + 1], w2p[1][0][0], bo2[1]);
            a1     = __dp4a(YH[p + 1], w2p[1][0][1], a1);
            a1     = __dp4a(YL[p + 2], w2p[1][1][0], a1);
            a1     = __dp4a(YH[p + 2], w2p[1][1][1], a1);
            a1     = __dp4a(YL[p + 3], w2p[1][2][0], a1);
            a1     = __dp4a(YH[p + 3], w2p[1][2][1], a1);
            f0[p] = (float)min(max(a0 >> 7, -128), 127) * 0.0078125f;
            f1[p] = (float)min(max(a1 >> 7, -128), 127) * 0.0078125f;
        }
        *(float4*)(ob + ts + j)             = make_float4(f0[0], f0[1], f0[2], f0[3]);
        *(float4*)(ob + (size_t)L + ts + j) = make_float4(f1[0], f1[1], f1[2], f1[3]);
    }
}

extern "C" void kernel_launch(void* const* d_in, const int* in_sizes, int n_in,
                              void* d_out, int out_size)
{
    const float* x       = (const float*)d_in[0];
    const float* w1      = (const float*)d_in[1];
    const float* b1      = (const float*)d_in[2];
    const float* gamma   = (const float*)d_in[3];
    const float* beta    = (const float*)d_in[4];
    const float* bn_mean = (const float*)d_in[5];
    const float* bn_var  = (const float*)d_in[6];
    const float* w2      = (const float*)d_in[7];
    const float* b2      = (const float*)d_in[8];
    float* out = (float*)d_out;

    const int B = 16;
    const int L = in_sizes[0] / (B * 4);

    const int smem_bytes = ((TL + 8) + 2 * (TL + 4)) * (int)sizeof(int); // 24.6KB

    dim3 grid((L + TL - 1) / TL, B);
    fused_qconv_i8o<<<grid, NT, smem_bytes>>>(
        x, w1, b1, gamma, beta, bn_mean, bn_var, w2, b2, out, L);
}